// round 4
// baseline (speedup 1.0000x reference)
#include <cuda_runtime.h>
#include <cstddef>

// Problem: out[b,i,j] = sorted-pair-permute of v (B=8, L=4096, D=1024 fp32).
// Factored form:
//   w[r] = min(v[r], v[r+1]) for even r, max for odd r  (adjacent-pair sort)
//   out[i,j] = w[(i - s_j) mod L, j],  s_0 = 0, s_j = 2*(j-1) for j >= 1
// Since max s = 2*1022 = 2044 < L, there is no mod-wrap in s itself.
//
// Tiling: each CTA handles a [R x C] output tile (R=256 rows, C=32 cols).
// Shift spread within a 32-col tile is <= 62, so we stage a band of
// R+64 = 320 source rows x 32 cols in shared memory (40 KB, static).
// Loads and stores are fully coalesced 128B segments; smem consume reads
// are conflict-free (bank == lane).

namespace {
constexpr int L    = 4096;
constexpr int D    = 1024;
constexpr int C    = 32;    // columns per tile
constexpr int R    = 256;   // output rows per tile (even)
constexpr int BAND = R + 64;
constexpr int NTHREADS = 512;  // 16 warps
constexpr int NWARPS   = NTHREADS / 32;
}

__global__ __launch_bounds__(NTHREADS)
void swd_kernel(const float* __restrict__ v, float* __restrict__ out) {
    __shared__ float sband[BAND][C];

    const int j0 = blockIdx.x * C;       // column tile base
    const int i0 = blockIdx.y * R;       // output row tile base (even)
    const int b  = blockIdx.z;

    const int lane = threadIdx.x & 31;
    const int w    = threadIdx.x >> 5;

    // shift for column j (monotone in j, even, no wrap)
    const int j_hi     = j0 + C - 1;
    const int shift_hi = (j_hi == 0) ? 0 : 2 * (j_hi - 1);
    // Band covers global rows [i0 - shift_hi, i0 - shift_hi + BAND) mod L.
    const int band_base = i0 - shift_hi;   // even; may be negative

    const float* __restrict__ vb = v   + (size_t)b * L * D;
    float*       __restrict__ ob = out + (size_t)b * L * D;

    // ---- Load band: coalesced (32 consecutive floats per warp-row) ----
    #pragma unroll 4
    for (int rr = w; rr < BAND; rr += NWARPS) {
        int g = (band_base + rr + L) & (L - 1);
        sband[rr][lane] = vb[(size_t)g * D + j0 + lane];
    }
    __syncthreads();

    // ---- Consume: each thread emits one (min,max) output pair per step ----
    const int j  = j0 + lane;
    const int sj = (j == 0) ? 0 : 2 * (j - 1);
    const int off = shift_hi - sj;   // in [0, 62], even

    #pragma unroll 4
    for (int p = w; p < R / 2; p += NWARPS) {
        const int i   = i0 + 2 * p;          // even output row
        const int idx = 2 * p + off;         // even band row of the pair
        float a = sband[idx][lane];
        float c = sband[idx + 1][lane];
        float lo = fminf(a, c);
        float hi = fmaxf(a, c);
        ob[(size_t)i * D + j]       = lo;
        ob[(size_t)(i + 1) * D + j] = hi;
    }
}

extern "C" void kernel_launch(void* const* d_in, const int* in_sizes, int n_in,
                              void* d_out, int out_size) {
    const float* v = (const float*)d_in[0];
    float* out = (float*)d_out;
    const int B = in_sizes[0] / (L * D);

    dim3 grid(D / C, L / R, B);   // 32 x 16 x 8 = 4096 CTAs
    swd_kernel<<<grid, NTHREADS>>>(v, out);
}

// round 5
// speedup vs baseline: 1.0776x; 1.0776x over previous
#include <cuda_runtime.h>
#include <cstddef>

// out[b,i,j]: pairwise-sorted, per-column cyclically shifted v.
//   s_j = (j==0) ? 0 : 2*(j-1)   (always even)
//   out pair (i, i+1), i even:  sort( v[(i-s_j)%L, j], v[(i+1-s_j)%L, j] )
//
// Tile: R=256 output rows x C=32 cols per CTA.
// Smem holds the band PRE-SHIFTED per column: smem row for column j storing
// global row g is  g - (i0 - s_j)  in [0, R).  Pair windows then align across
// columns -> consume does 8 scalar LDS + 2x STG.128 per thread.
// Load does LDG.128 + 4 predicated scalar STS (conflict-free with stride 33).

namespace {
constexpr int L      = 4096;
constexpr int D      = 1024;
constexpr int C      = 32;    // columns per tile
constexpr int R      = 256;   // output rows per tile (even, divides L)
constexpr int STRIDE = 33;    // padded smem row stride in floats
constexpr int BAND   = R + 64; // load-loop row count (covers R-1 + max off = 317)
constexpr int NT     = 512;   // threads per CTA
}

__global__ __launch_bounds__(NT)
void swd_kernel(const float* __restrict__ v, float* __restrict__ out) {
    __shared__ float s[R * STRIDE];   // 33792 bytes

    const int j0 = blockIdx.x * C;    // column tile base
    const int i0 = blockIdx.y * R;    // output row tile base (even)
    const int b  = blockIdx.z;

    const int q  = threadIdx.x & 7;   // col quad within tile (4 cols)
    const int tr = threadIdx.x >> 3;  // 0..63

    // Largest shift in this tile (j_hi >= 31, so always the j>=1 formula)
    const int j_hi      = j0 + C - 1;
    const int shift_hi  = 2 * (j_hi - 1);
    const int band_base = i0 - shift_hi;          // may be negative

    const float* __restrict__ vb = v   + (size_t)b * (L * D);
    float*       __restrict__ ob = out + (size_t)b * (L * D);

    const int cb = 4 * q;             // tile-local col base of this quad

    // Per-column row offset within the band: off_k = shift_hi - s_{j0+cb+k}
    int off_[4];
    #pragma unroll
    for (int k = 0; k < 4; k++) {
        int j  = j0 + cb + k;
        int sj = (j == 0) ? 0 : 2 * (j - 1);
        off_[k] = shift_hi - sj;      // in [0, 62], even
    }

    // ---- Load band: LDG.128 + 4 predicated scalar STS (pre-shifted rows) ----
    #pragma unroll
    for (int it = 0; it < BAND / 64; it++) {      // 5 iterations
        int rr = it * 64 + tr;                    // band row 0..319
        int g  = (band_base + rr) & (L - 1);
        float4 val = *reinterpret_cast<const float4*>(vb + (size_t)g * D + (j0 + cb));
        float vv[4] = {val.x, val.y, val.z, val.w};
        #pragma unroll
        for (int k = 0; k < 4; k++) {
            int srow = rr - off_[k];
            if (0 <= srow && srow < R)
                s[srow * STRIDE + cb + k] = vv[k];
        }
    }
    __syncthreads();

    // ---- Consume: each thread -> one pair x 4 cols; 2x STG.128 ----
    #pragma unroll
    for (int it = 0; it < (R / 2) * 8 / NT; it++) {   // 2 iterations
        int p = it * 64 + tr;                          // pair 0..127
        const float* r0 = s + (2 * p) * STRIDE + cb;
        const float* r1 = r0 + STRIDE;
        float a0 = r0[0], a1 = r0[1], a2 = r0[2], a3 = r0[3];
        float b0 = r1[0], b1 = r1[1], b2 = r1[2], b3 = r1[3];
        float4 lo, hi;
        lo.x = fminf(a0, b0); hi.x = fmaxf(a0, b0);
        lo.y = fminf(a1, b1); hi.y = fmaxf(a1, b1);
        lo.z = fminf(a2, b2); hi.z = fmaxf(a2, b2);
        lo.w = fminf(a3, b3); hi.w = fmaxf(a3, b3);
        float* dst = ob + (size_t)(i0 + 2 * p) * D + (j0 + cb);
        __stcs(reinterpret_cast<float4*>(dst),     lo);
        __stcs(reinterpret_cast<float4*>(dst + D), hi);
    }
}

extern "C" void kernel_launch(void* const* d_in, const int* in_sizes, int n_in,
                              void* d_out, int out_size) {
    const float* v   = (const float*)d_in[0];
    float*       out = (float*)d_out;
    const int B = in_sizes[0] / (L * D);

    dim3 grid(D / C, L / R, B);   // 32 x 16 x B
    swd_kernel<<<grid, NT>>>(v, out);
}